// round 1
// baseline (speedup 1.0000x reference)
#include <cuda_runtime.h>
#include <cuda_bf16.h>
#include <cstdint>

// Problem constants
#define BB 2
#define SS 2048
#define DD 1024
#define HH 16
#define HD 64
#define D3 3072
#define MROWS (BB * SS)          // 4096
#define SCALE 0.03125f           // 1/sqrt(1024)
#define LN_EPS 1e-5f

// ---------------------------------------------------------------------------
// Scratch (no allocation allowed -> __device__ globals)
// ---------------------------------------------------------------------------
__device__ float g_qkv[MROWS * D3];     // 48 MB
__device__ float g_o[MROWS * DD];       // 16 MB  (attention output, [b,s,h*hd])
__device__ float g_y[MROWS * DD];       // 16 MB  (proj + residual)

// ---------------------------------------------------------------------------
// SGEMM: C[M,N] = A[M,K] @ W[N,K]^T + bias[N] (+ resid[M,N])
// 128x128 tile, BK=8, 256 threads, 8x8 per thread.
// ---------------------------------------------------------------------------
__global__ __launch_bounds__(256) void sgemm128(
    const float* __restrict__ A, const float* __restrict__ W,
    const float* __restrict__ bias, const float* __restrict__ resid,
    float* __restrict__ C, int M, int N, int K)
{
    __shared__ float As[8][132];
    __shared__ float Bs[8][132];

    const int tid = threadIdx.x;
    const int tx = tid & 15;          // 0..15  -> n
    const int ty = tid >> 4;          // 0..15  -> m
    const int m0 = blockIdx.y * 128;
    const int n0 = blockIdx.x * 128;

    const int lr = tid >> 1;          // 0..127 row within tile
    const int lk = (tid & 1) * 4;     // 0 or 4

    const float* Ap = A + (size_t)(m0 + lr) * K + lk;
    const float* Wp = W + (size_t)(n0 + lr) * K + lk;

    float acc[8][8];
#pragma unroll
    for (int i = 0; i < 8; i++)
#pragma unroll
        for (int j = 0; j < 8; j++) acc[i][j] = 0.f;

    for (int k0 = 0; k0 < K; k0 += 8) {
        float4 av = *(const float4*)(Ap + k0);
        float4 bv = *(const float4*)(Wp + k0);
        As[lk + 0][lr] = av.x; As[lk + 1][lr] = av.y;
        As[lk + 2][lr] = av.z; As[lk + 3][lr] = av.w;
        Bs[lk + 0][lr] = bv.x; Bs[lk + 1][lr] = bv.y;
        Bs[lk + 2][lr] = bv.z; Bs[lk + 3][lr] = bv.w;
        __syncthreads();

#pragma unroll
        for (int kk = 0; kk < 8; kk++) {
            float a[8], b[8];
            *(float4*)(a)     = *(const float4*)&As[kk][ty * 8];
            *(float4*)(a + 4) = *(const float4*)&As[kk][ty * 8 + 4];
            *(float4*)(b)     = *(const float4*)&Bs[kk][tx * 8];
            *(float4*)(b + 4) = *(const float4*)&Bs[kk][tx * 8 + 4];
#pragma unroll
            for (int i = 0; i < 8; i++)
#pragma unroll
                for (int j = 0; j < 8; j++)
                    acc[i][j] = fmaf(a[i], b[j], acc[i][j]);
        }
        __syncthreads();
    }

    // Epilogue: bias (+ residual), vectorized stores
    const int n = n0 + tx * 8;
    float4 bia0 = *(const float4*)(bias + n);
    float4 bia1 = *(const float4*)(bias + n + 4);
#pragma unroll
    for (int i = 0; i < 8; i++) {
        const int m = m0 + ty * 8 + i;
        float4 v0, v1;
        v0.x = acc[i][0] + bia0.x; v0.y = acc[i][1] + bia0.y;
        v0.z = acc[i][2] + bia0.z; v0.w = acc[i][3] + bia0.w;
        v1.x = acc[i][4] + bia1.x; v1.y = acc[i][5] + bia1.y;
        v1.z = acc[i][6] + bia1.z; v1.w = acc[i][7] + bia1.w;
        if (resid) {
            float4 r0 = *(const float4*)(resid + (size_t)m * N + n);
            float4 r1 = *(const float4*)(resid + (size_t)m * N + n + 4);
            v0.x += r0.x; v0.y += r0.y; v0.z += r0.z; v0.w += r0.w;
            v1.x += r1.x; v1.y += r1.y; v1.z += r1.z; v1.w += r1.w;
        }
        *(float4*)(C + (size_t)m * N + n)     = v0;
        *(float4*)(C + (size_t)m * N + n + 4) = v1;
    }
}

// ---------------------------------------------------------------------------
// Flash attention (fp32), causal + relative position bias.
// Block: (qt, h, b). 256 threads, 64 q-rows, 64-wide K tiles, 4x4 microtile.
// Dynamic smem: Qs/Ks/Vs/Ps each 64x65 floats.
// ---------------------------------------------------------------------------
#define AT_STR 65
#define AT_BUF (64 * AT_STR)
#define SMEM_ATTN (4 * AT_BUF * 4)

__global__ __launch_bounds__(256) void attn64(
    const float* __restrict__ qkv, const float* __restrict__ rpb,
    float* __restrict__ obuf)
{
    extern __shared__ float sm[];
    float* Qs = sm;
    float* Ks = sm + AT_BUF;
    float* Vs = sm + 2 * AT_BUF;
    float* Ps = sm + 3 * AT_BUF;

    const int qt = blockIdx.x;
    const int h  = blockIdx.y;
    const int b  = blockIdx.z;
    const int tid = threadIdx.x;
    const int tx = tid & 15;
    const int ty = tid >> 4;
    const int q0 = qt * 64;

    // Load Q tile [64 rows][64 d]
    for (int it = tid; it < 1024; it += 256) {
        const int r = it >> 4, c = (it & 15) * 4;
        float4 v = *(const float4*)(qkv + (size_t)(b * SS + q0 + r) * D3 + h * HD + c);
        Qs[r * AT_STR + c + 0] = v.x; Qs[r * AT_STR + c + 1] = v.y;
        Qs[r * AT_STR + c + 2] = v.z; Qs[r * AT_STR + c + 3] = v.w;
    }

    float m[4], l[4], o[4][4];
#pragma unroll
    for (int i = 0; i < 4; i++) {
        m[i] = -1e30f; l[i] = 0.f;
#pragma unroll
        for (int j = 0; j < 4; j++) o[i][j] = 0.f;
    }
    __syncthreads();

    for (int kt = 0; kt <= qt; kt++) {
        // Load K and V tiles
        for (int it = tid; it < 1024; it += 256) {
            const int r = it >> 4, c = (it & 15) * 4;
            const size_t base = (size_t)(b * SS + kt * 64 + r) * D3 + h * HD;
            float4 kv = *(const float4*)(qkv + base + DD + c);
            float4 vv = *(const float4*)(qkv + base + 2 * DD + c);
            Ks[r * AT_STR + c + 0] = kv.x; Ks[r * AT_STR + c + 1] = kv.y;
            Ks[r * AT_STR + c + 2] = kv.z; Ks[r * AT_STR + c + 3] = kv.w;
            Vs[r * AT_STR + c + 0] = vv.x; Vs[r * AT_STR + c + 1] = vv.y;
            Vs[r * AT_STR + c + 2] = vv.z; Vs[r * AT_STR + c + 3] = vv.w;
        }
        __syncthreads();

        // Scores: s[i][j] = Q[4ty+i] . K[4tx+j]
        float s[4][4];
#pragma unroll
        for (int i = 0; i < 4; i++)
#pragma unroll
            for (int j = 0; j < 4; j++) s[i][j] = 0.f;

#pragma unroll 4
        for (int kk = 0; kk < 64; kk++) {
            float a[4], bb[4];
#pragma unroll
            for (int i = 0; i < 4; i++) a[i]  = Qs[(4 * ty + i) * AT_STR + kk];
#pragma unroll
            for (int j = 0; j < 4; j++) bb[j] = Ks[(4 * tx + j) * AT_STR + kk];
#pragma unroll
            for (int i = 0; i < 4; i++)
#pragma unroll
                for (int j = 0; j < 4; j++)
                    s[i][j] = fmaf(a[i], bb[j], s[i][j]);
        }

        // Scale + bias + causal mask
#pragma unroll
        for (int i = 0; i < 4; i++) {
            const int qp = q0 + 4 * ty + i;
#pragma unroll
            for (int j = 0; j < 4; j++) {
                const int kp = kt * 64 + 4 * tx + j;
                float val = s[i][j] * SCALE + rpb[(kp - qp + SS - 1) * HH + h];
                if (kp > qp) val = -1e30f;
                s[i][j] = val;
            }
        }

        // Online softmax
        float rmax[4], rsum[4], p[4][4], alpha[4], mn[4];
#pragma unroll
        for (int i = 0; i < 4; i++) {
            rmax[i] = fmaxf(fmaxf(s[i][0], s[i][1]), fmaxf(s[i][2], s[i][3]));
#pragma unroll
            for (int off = 8; off > 0; off >>= 1)
                rmax[i] = fmaxf(rmax[i], __shfl_xor_sync(0xffffffffu, rmax[i], off, 16));
            mn[i] = fmaxf(m[i], rmax[i]);
            alpha[i] = __expf(m[i] - mn[i]);
            m[i] = mn[i];
            rsum[i] = 0.f;
#pragma unroll
            for (int j = 0; j < 4; j++) {
                p[i][j] = __expf(s[i][j] - mn[i]);
                rsum[i] += p[i][j];
            }
#pragma unroll
            for (int off = 8; off > 0; off >>= 1)
                rsum[i] += __shfl_xor_sync(0xffffffffu, rsum[i], off, 16);
            l[i] = l[i] * alpha[i] + rsum[i];
#pragma unroll
            for (int j = 0; j < 4; j++) o[i][j] *= alpha[i];
        }

        // Write P tile
#pragma unroll
        for (int i = 0; i < 4; i++)
#pragma unroll
            for (int j = 0; j < 4; j++)
                Ps[(4 * ty + i) * AT_STR + 4 * tx + j] = p[i][j];
        __syncthreads();

        // O += P @ V
#pragma unroll 4
        for (int kk = 0; kk < 64; kk++) {
            float pv[4], vv[4];
#pragma unroll
            for (int i = 0; i < 4; i++) pv[i] = Ps[(4 * ty + i) * AT_STR + kk];
#pragma unroll
            for (int j = 0; j < 4; j++) vv[j] = Vs[kk * AT_STR + 4 * tx + j];
#pragma unroll
            for (int i = 0; i < 4; i++)
#pragma unroll
                for (int j = 0; j < 4; j++)
                    o[i][j] = fmaf(pv[i], vv[j], o[i][j]);
        }
        __syncthreads();
    }

    // Normalize + write out: obuf layout [b, s, h*hd + d]
#pragma unroll
    for (int i = 0; i < 4; i++) {
        const float inv = 1.f / l[i];
        const size_t base = (size_t)(b * SS + q0 + 4 * ty + i) * DD + h * HD + 4 * tx;
#pragma unroll
        for (int j = 0; j < 4; j++)
            obuf[base + j] = o[i][j] * inv;
    }
}

// ---------------------------------------------------------------------------
// LayerNorm over D=1024, one block per row, 256 threads x 4 elems
// ---------------------------------------------------------------------------
__global__ __launch_bounds__(256) void layernorm_k(
    const float* __restrict__ y, const float* __restrict__ g,
    const float* __restrict__ bta, float* __restrict__ out)
{
    const int row = blockIdx.x;
    const int t = threadIdx.x;
    const float4 v = *(const float4*)(y + (size_t)row * DD + t * 4);

    float s  = v.x + v.y + v.z + v.w;
    float sq = v.x * v.x + v.y * v.y + v.z * v.z + v.w * v.w;
#pragma unroll
    for (int off = 16; off > 0; off >>= 1) {
        s  += __shfl_xor_sync(0xffffffffu, s, off);
        sq += __shfl_xor_sync(0xffffffffu, sq, off);
    }
    __shared__ float ss[8], sqq[8];
    if ((t & 31) == 0) { ss[t >> 5] = s; sqq[t >> 5] = sq; }
    __syncthreads();
    float tot = 0.f, totq = 0.f;
#pragma unroll
    for (int i = 0; i < 8; i++) { tot += ss[i]; totq += sqq[i]; }
    const float mu  = tot * (1.f / DD);
    const float var = totq * (1.f / DD) - mu * mu;
    const float r   = rsqrtf(var + LN_EPS);

    const float4 gg = *(const float4*)(g + t * 4);
    const float4 bb = *(const float4*)(bta + t * 4);
    float4 o4;
    o4.x = (v.x - mu) * r * gg.x + bb.x;
    o4.y = (v.y - mu) * r * gg.y + bb.y;
    o4.z = (v.z - mu) * r * gg.z + bb.z;
    o4.w = (v.w - mu) * r * gg.w + bb.w;
    *(float4*)(out + (size_t)row * DD + t * 4) = o4;
}

// ---------------------------------------------------------------------------
// Launch
// ---------------------------------------------------------------------------
extern "C" void kernel_launch(void* const* d_in, const int* in_sizes, int n_in,
                              void* d_out, int out_size)
{
    const float* x      = (const float*)d_in[0];  // [B,S,D]
    const float* W_w    = (const float*)d_in[1];  // [3D,D]
    const float* W_b    = (const float*)d_in[2];  // [3D]
    const float* proj_w = (const float*)d_in[3];  // [D,D]
    const float* proj_b = (const float*)d_in[4];  // [D]
    const float* ln_g   = (const float*)d_in[5];  // [D]
    const float* ln_b   = (const float*)d_in[6];  // [D]
    const float* rpb    = (const float*)d_in[7];  // [2S-1,H]
    float* out = (float*)d_out;

    float *qkv, *obuf, *ybuf;
    cudaGetSymbolAddress((void**)&qkv,  g_qkv);
    cudaGetSymbolAddress((void**)&obuf, g_o);
    cudaGetSymbolAddress((void**)&ybuf, g_y);

    // 1) QKV projection: [4096,3072] = x @ W_w^T + W_b
    {
        dim3 grid(D3 / 128, MROWS / 128);
        sgemm128<<<grid, 256>>>(x, W_w, W_b, nullptr, qkv, MROWS, D3, DD);
    }

    // 2) Flash attention
    {
        cudaFuncSetAttribute(attn64, cudaFuncAttributeMaxDynamicSharedMemorySize, SMEM_ATTN);
        dim3 grid(SS / 64, HH, BB);
        attn64<<<grid, 256, SMEM_ATTN>>>(qkv, rpb, obuf);
    }

    // 3) Output projection + residual: y = o @ proj_w^T + proj_b + x
    {
        dim3 grid(DD / 128, MROWS / 128);
        sgemm128<<<grid, 256>>>(obuf, proj_w, proj_b, x, ybuf, MROWS, DD, DD);
    }

    // 4) LayerNorm
    layernorm_k<<<MROWS, 256>>>(ybuf, ln_g, ln_b, out);
}

// round 3
// speedup vs baseline: 1.5124x; 1.5124x over previous
#include <cuda_runtime.h>
#include <cuda_bf16.h>
#include <cstdint>

// Problem constants
#define BB 2
#define SS 2048
#define DD 1024
#define HH 16
#define HD 64
#define D3 3072
#define MROWS (BB * SS)          // 4096
#define SCALE 0.03125f           // 1/sqrt(1024)
#define LN_EPS 1e-5f

// ---------------------------------------------------------------------------
// Scratch (no allocation allowed -> __device__ globals)
// ---------------------------------------------------------------------------
__device__ float g_qkv[MROWS * D3];     // 48 MB
__device__ float g_o[MROWS * DD];       // 16 MB  (attention output)
__device__ float g_y[MROWS * DD];       // 16 MB  (proj + residual)

// ---------------------------------------------------------------------------
// Portable helpers (sm_80+ only; NO sm_100a-gated instructions)
// ---------------------------------------------------------------------------
__device__ __forceinline__ uint32_t smem_u32(const void* p) {
    uint32_t a;
    asm("{ .reg .u64 t; cvta.to.shared.u64 t, %1; cvt.u32.u64 %0, t; }"
        : "=r"(a) : "l"(p));
    return a;
}

__device__ __forceinline__ void cp16(uint32_t dst, const void* src) {
    asm volatile("cp.async.ca.shared.global [%0], [%1], 16;"
                 :: "r"(dst), "l"(src) : "memory");
}
#define CP_COMMIT() asm volatile("cp.async.commit_group;" ::: "memory")
#define CP_WAIT1()  asm volatile("cp.async.wait_group 1;" ::: "memory")
#define CP_WAIT0()  asm volatile("cp.async.wait_group 0;" ::: "memory")

__device__ __forceinline__ uint32_t f2tf(float f) {
    uint32_t r;
    asm("cvt.rna.tf32.f32 %0, %1;" : "=r"(r) : "f"(f));
    return r;
}

__device__ __forceinline__ void mma_tf32(
    float* c, const uint32_t* a, const uint32_t* b)
{
    asm volatile(
        "mma.sync.aligned.m16n8k8.row.col.f32.tf32.tf32.f32 "
        "{%0,%1,%2,%3}, {%4,%5,%6,%7}, {%8,%9}, {%0,%1,%2,%3};"
        : "+f"(c[0]), "+f"(c[1]), "+f"(c[2]), "+f"(c[3])
        : "r"(a[0]), "r"(a[1]), "r"(a[2]), "r"(a[3]),
          "r"(b[0]), "r"(b[1]));
}

// ===========================================================================
// TF32 mma.sync GEMM: C[M,N] = A[M,K] @ W[N,K]^T + bias (+ resid)
// CTA 128x128, BK=32, 8 warps (4M x 2N), warp tile 32x64 (2x8 m16n8k8).
// Smem rows padded to 36 floats -> conflict-free fragment loads.
// ===========================================================================
#define GK 32
#define GPAD 36
#define GTILE_FLOATS (128 * GPAD)                 // per buffer
#define GTILE_BYTES  (GTILE_FLOATS * 4)           // 18432
#define GEMM_SMEM    (4 * GTILE_BYTES)            // A0,A1,B0,B1 = 73728

__global__ __launch_bounds__(256) void gemm_tf32(
    const float* __restrict__ A, const float* __restrict__ W,
    const float* __restrict__ bias, const float* __restrict__ resid,
    float* __restrict__ C, int M, int N, int K)
{
    extern __shared__ float sm[];
    float* As[2] = { sm,                  sm + GTILE_FLOATS };
    float* Bs[2] = { sm + 2*GTILE_FLOATS, sm + 3*GTILE_FLOATS };
    const uint32_t sA[2] = { smem_u32(As[0]), smem_u32(As[1]) };
    const uint32_t sB[2] = { smem_u32(Bs[0]), smem_u32(Bs[1]) };

    const int tid  = threadIdx.x;
    const int lane = tid & 31;
    const int wid  = tid >> 5;
    const int g    = lane >> 2;      // group 0..7
    const int c    = lane & 3;       // thread-in-group 0..3
    const int wm0  = (wid & 3) * 32; // warp M offset in tile
    const int wn0  = (wid >> 2) * 64;// warp N offset in tile
    const int m0   = blockIdx.y * 128;
    const int n0   = blockIdx.x * 128;

    // Global load mapping: 1024 float4 per tile, 4 per thread
    const int lrow = tid >> 3;               // tid maps rows 0..31 step... (idx>>3)
    const int lq   = tid & 7;                // 16B quad within 128B row

    float acc[2][8][4];
#pragma unroll
    for (int mt = 0; mt < 2; mt++)
#pragma unroll
        for (int nt = 0; nt < 8; nt++)
#pragma unroll
            for (int k = 0; k < 4; k++) acc[mt][nt][k] = 0.f;

    const int nch = K >> 5;

    // --- async load of chunk i into stage st ---
    auto load_chunk = [&](int i, int st) {
        const float* Ag = A + (size_t)m0 * K + i * GK;
        const float* Wg = W + (size_t)n0 * K + i * GK;
#pragma unroll
        for (int t = 0; t < 4; t++) {
            const int idx = tid + t * 256;
            const int row = idx >> 3;
            const int q   = idx & 7;
            const uint32_t off = (uint32_t)(row * GPAD + q * 4) * 4u;
            cp16(sA[st] + off, Ag + (size_t)row * K + q * 4);
            cp16(sB[st] + off, Wg + (size_t)row * K + q * 4);
        }
        CP_COMMIT();
    };

    load_chunk(0, 0);

    for (int i = 0; i < nch; i++) {
        const int st = i & 1;
        if (i + 1 < nch) { load_chunk(i + 1, st ^ 1); CP_WAIT1(); }
        else             { CP_WAIT0(); }
        __syncthreads();

        const float* Af = As[st];
        const float* Bf = Bs[st];
#pragma unroll
        for (int kk = 0; kk < GK; kk += 8) {
            uint32_t af[2][4];
#pragma unroll
            for (int mt = 0; mt < 2; mt++) {
                const int m = wm0 + mt * 16 + g;
                af[mt][0] = f2tf(Af[(m    ) * GPAD + kk + c    ]);
                af[mt][1] = f2tf(Af[(m + 8) * GPAD + kk + c    ]);
                af[mt][2] = f2tf(Af[(m    ) * GPAD + kk + c + 4]);
                af[mt][3] = f2tf(Af[(m + 8) * GPAD + kk + c + 4]);
            }
            uint32_t bf[8][2];
#pragma unroll
            for (int nt = 0; nt < 8; nt++) {
                const int n = wn0 + nt * 8 + g;
                bf[nt][0] = f2tf(Bf[n * GPAD + kk + c    ]);
                bf[nt][1] = f2tf(Bf[n * GPAD + kk + c + 4]);
            }
#pragma unroll
            for (int mt = 0; mt < 2; mt++)
#pragma unroll
                for (int nt = 0; nt < 8; nt++)
                    mma_tf32(acc[mt][nt], af[mt], bf[nt]);
        }
        __syncthreads();
    }

    // Epilogue: c0,c1 -> (row, col..col+1); c2,c3 -> (row+8, ...)
#pragma unroll
    for (int mt = 0; mt < 2; mt++) {
#pragma unroll
        for (int hrow = 0; hrow < 2; hrow++) {
            const int m = m0 + wm0 + mt * 16 + g + hrow * 8;
#pragma unroll
            for (int nt = 0; nt < 8; nt++) {
                const int col = n0 + wn0 + nt * 8 + c * 2;
                float2 bi = *(const float2*)(bias + col);
                float2 v;
                v.x = acc[mt][nt][hrow * 2 + 0] + bi.x;
                v.y = acc[mt][nt][hrow * 2 + 1] + bi.y;
                if (resid) {
                    float2 r = *(const float2*)(resid + (size_t)m * N + col);
                    v.x += r.x; v.y += r.y;
                }
                *(float2*)(C + (size_t)m * N + col) = v;
            }
        }
    }
    (void)lrow; (void)lq;
}

// ---------------------------------------------------------------------------
// Flash attention (fp32), causal + relative position bias. (R1, passing)
// ---------------------------------------------------------------------------
#define AT_STR 65
#define AT_BUF (64 * AT_STR)
#define SMEM_ATTN (4 * AT_BUF * 4)

__global__ __launch_bounds__(256) void attn64(
    const float* __restrict__ qkv, const float* __restrict__ rpb,
    float* __restrict__ obuf)
{
    extern __shared__ float smf[];
    float* Qs = smf;
    float* Ks = smf + AT_BUF;
    float* Vs = smf + 2 * AT_BUF;
    float* Ps = smf + 3 * AT_BUF;

    const int qt = blockIdx.x;
    const int h  = blockIdx.y;
    const int b  = blockIdx.z;
    const int tid = threadIdx.x;
    const int tx = tid & 15;
    const int ty = tid >> 4;
    const int q0 = qt * 64;

    for (int it = tid; it < 1024; it += 256) {
        const int r = it >> 4, cc = (it & 15) * 4;
        float4 v = *(const float4*)(qkv + (size_t)(b * SS + q0 + r) * D3 + h * HD + cc);
        Qs[r * AT_STR + cc + 0] = v.x; Qs[r * AT_STR + cc + 1] = v.y;
        Qs[r * AT_STR + cc + 2] = v.z; Qs[r * AT_STR + cc + 3] = v.w;
    }

    float m[4], l[4], o[4][4];
#pragma unroll
    for (int i = 0; i < 4; i++) {
        m[i] = -1e30f; l[i] = 0.f;
#pragma unroll
        for (int j = 0; j < 4; j++) o[i][j] = 0.f;
    }
    __syncthreads();

    for (int kt = 0; kt <= qt; kt++) {
        for (int it = tid; it < 1024; it += 256) {
            const int r = it >> 4, cc = (it & 15) * 4;
            const size_t base = (size_t)(b * SS + kt * 64 + r) * D3 + h * HD;
            float4 kv = *(const float4*)(qkv + base + DD + cc);
            float4 vv = *(const float4*)(qkv + base + 2 * DD + cc);
            Ks[r * AT_STR + cc + 0] = kv.x; Ks[r * AT_STR + cc + 1] = kv.y;
            Ks[r * AT_STR + cc + 2] = kv.z; Ks[r * AT_STR + cc + 3] = kv.w;
            Vs[r * AT_STR + cc + 0] = vv.x; Vs[r * AT_STR + cc + 1] = vv.y;
            Vs[r * AT_STR + cc + 2] = vv.z; Vs[r * AT_STR + cc + 3] = vv.w;
        }
        __syncthreads();

        float s[4][4];
#pragma unroll
        for (int i = 0; i < 4; i++)
#pragma unroll
            for (int j = 0; j < 4; j++) s[i][j] = 0.f;

#pragma unroll 4
        for (int kk = 0; kk < 64; kk++) {
            float a[4], bb[4];
#pragma unroll
            for (int i = 0; i < 4; i++) a[i]  = Qs[(4 * ty + i) * AT_STR + kk];
#pragma unroll
            for (int j = 0; j < 4; j++) bb[j] = Ks[(4 * tx + j) * AT_STR + kk];
#pragma unroll
            for (int i = 0; i < 4; i++)
#pragma unroll
                for (int j = 0; j < 4; j++)
                    s[i][j] = fmaf(a[i], bb[j], s[i][j]);
        }

#pragma unroll
        for (int i = 0; i < 4; i++) {
            const int qp = q0 + 4 * ty + i;
#pragma unroll
            for (int j = 0; j < 4; j++) {
                const int kp = kt * 64 + 4 * tx + j;
                float val = s[i][j] * SCALE + rpb[(kp - qp + SS - 1) * HH + h];
                if (kp > qp) val = -1e30f;
                s[i][j] = val;
            }
        }

        float rmax[4], rsum[4], p[4][4], alpha[4], mn[4];
#pragma unroll
        for (int i = 0; i < 4; i++) {
            rmax[i] = fmaxf(fmaxf(s[i][0], s[i][1]), fmaxf(s[i][2], s[i][3]));
#pragma unroll
            for (int off = 8; off > 0; off >>= 1)
                rmax[i] = fmaxf(rmax[i], __shfl_xor_sync(0xffffffffu, rmax[i], off, 16));
            mn[i] = fmaxf(m[i], rmax[i]);
            alpha[i] = __expf(m[i] - mn[i]);
            m[i] = mn[i];
            rsum[i] = 0.f;
#pragma unroll
            for (int j = 0; j < 4; j++) {
                p[i][j] = __expf(s[i][j] - mn[i]);
                rsum[i] += p[i][j];
            }
#pragma unroll
            for (int off = 8; off > 0; off >>= 1)
                rsum[i] += __shfl_xor_sync(0xffffffffu, rsum[i], off, 16);
            l[i] = l[i] * alpha[i] + rsum[i];
#pragma unroll
            for (int j = 0; j < 4; j++) o[i][j] *= alpha[i];
        }

#pragma unroll
        for (int i = 0; i < 4; i++)
#pragma unroll
            for (int j = 0; j < 4; j++)
                Ps[(4 * ty + i) * AT_STR + 4 * tx + j] = p[i][j];
        __syncthreads();

#pragma unroll 4
        for (int kk = 0; kk < 64; kk++) {
            float pv[4], vv[4];
#pragma unroll
            for (int i = 0; i < 4; i++) pv[i] = Ps[(4 * ty + i) * AT_STR + kk];
#pragma unroll
            for (int j = 0; j < 4; j++) vv[j] = Vs[kk * AT_STR + 4 * tx + j];
#pragma unroll
            for (int i = 0; i < 4; i++)
#pragma unroll
                for (int j = 0; j < 4; j++)
                    o[i][j] = fmaf(pv[i], vv[j], o[i][j]);
        }
        __syncthreads();
    }

#pragma unroll
    for (int i = 0; i < 4; i++) {
        const float inv = 1.f / l[i];
        const size_t base = (size_t)(b * SS + q0 + 4 * ty + i) * DD + h * HD + 4 * tx;
#pragma unroll
        for (int j = 0; j < 4; j++)
            obuf[base + j] = o[i][j] * inv;
    }
}

// ---------------------------------------------------------------------------
// LayerNorm over D=1024
// ---------------------------------------------------------------------------
__global__ __launch_bounds__(256) void layernorm_k(
    const float* __restrict__ y, const float* __restrict__ g,
    const float* __restrict__ bta, float* __restrict__ out)
{
    const int row = blockIdx.x;
    const int t = threadIdx.x;
    const float4 v = *(const float4*)(y + (size_t)row * DD + t * 4);

    float s  = v.x + v.y + v.z + v.w;
    float sq = v.x * v.x + v.y * v.y + v.z * v.z + v.w * v.w;
#pragma unroll
    for (int off = 16; off > 0; off >>= 1) {
        s  += __shfl_xor_sync(0xffffffffu, s, off);
        sq += __shfl_xor_sync(0xffffffffu, sq, off);
    }
    __shared__ float ss[8], sqq[8];
    if ((t & 31) == 0) { ss[t >> 5] = s; sqq[t >> 5] = sq; }
    __syncthreads();
    float tot = 0.f, totq = 0.f;
#pragma unroll
    for (int i = 0; i < 8; i++) { tot += ss[i]; totq += sqq[i]; }
    const float mu  = tot * (1.f / DD);
    const float var = totq * (1.f / DD) - mu * mu;
    const float r   = rsqrtf(var + LN_EPS);

    const float4 gg = *(const float4*)(g + t * 4);
    const float4 bb = *(const float4*)(bta + t * 4);
    float4 o4;
    o4.x = (v.x - mu) * r * gg.x + bb.x;
    o4.y = (v.y - mu) * r * gg.y + bb.y;
    o4.z = (v.z - mu) * r * gg.z + bb.z;
    o4.w = (v.w - mu) * r * gg.w + bb.w;
    *(float4*)(out + (size_t)row * DD + t * 4) = o4;
}

// ---------------------------------------------------------------------------
// Launch
// ---------------------------------------------------------------------------
extern "C" void kernel_launch(void* const* d_in, const int* in_sizes, int n_in,
                              void* d_out, int out_size)
{
    const float* x      = (const float*)d_in[0];  // [B,S,D]
    const float* W_w    = (const float*)d_in[1];  // [3D,D]
    const float* W_b    = (const float*)d_in[2];  // [3D]
    const float* proj_w = (const float*)d_in[3];  // [D,D]
    const float* proj_b = (const float*)d_in[4];  // [D]
    const float* ln_g   = (const float*)d_in[5];  // [D]
    const float* ln_b   = (const float*)d_in[6];  // [D]
    const float* rpb    = (const float*)d_in[7];  // [2S-1,H]
    float* out = (float*)d_out;

    float *qkv, *obuf, *ybuf;
    cudaGetSymbolAddress((void**)&qkv,  g_qkv);
    cudaGetSymbolAddress((void**)&obuf, g_o);
    cudaGetSymbolAddress((void**)&ybuf, g_y);

    cudaFuncSetAttribute(gemm_tf32, cudaFuncAttributeMaxDynamicSharedMemorySize, GEMM_SMEM);
    cudaFuncSetAttribute(attn64, cudaFuncAttributeMaxDynamicSharedMemorySize, SMEM_ATTN);

    // 1) QKV projection: [4096,3072] = x @ W_w^T + W_b
    {
        dim3 grid(D3 / 128, MROWS / 128);
        gemm_tf32<<<grid, 256, GEMM_SMEM>>>(x, W_w, W_b, nullptr, qkv, MROWS, D3, DD);
    }

    // 2) Flash attention
    {
        dim3 grid(SS / 64, HH, BB);
        attn64<<<grid, 256, SMEM_ATTN>>>(qkv, rpb, obuf);
    }

    // 3) Output projection + residual
    {
        dim3 grid(DD / 128, MROWS / 128);
        gemm_tf32<<<grid, 256, GEMM_SMEM>>>(obuf, proj_w, proj_b, x, ybuf, MROWS, DD, DD);
    }

    // 4) LayerNorm
    layernorm_k<<<MROWS, 256>>>(ybuf, ln_g, ln_b, out);
}

// round 4
// speedup vs baseline: 3.2843x; 2.1716x over previous
#include <cuda_runtime.h>
#include <cuda_bf16.h>
#include <cstdint>

// Problem constants
#define BB 2
#define SS 2048
#define DD 1024
#define HH 16
#define HD 64
#define D3 3072
#define MROWS (BB * SS)          // 4096
#define SCALE 0.03125f           // 1/sqrt(1024)
#define LOG2E 1.4426950408889634f
#define LN_EPS 1e-5f

// ---------------------------------------------------------------------------
// Scratch (no allocation allowed -> __device__ globals)
// ---------------------------------------------------------------------------
__device__ float g_qkv[MROWS * D3];     // 48 MB
__device__ float g_o[MROWS * DD];       // 16 MB  (attention output)
__device__ float g_y[MROWS * DD];       // 16 MB  (proj + residual)

// ---------------------------------------------------------------------------
// Portable helpers (sm_80+ only; NO sm_100a-gated instructions)
// ---------------------------------------------------------------------------
__device__ __forceinline__ uint32_t smem_u32(const void* p) {
    uint32_t a;
    asm("{ .reg .u64 t; cvta.to.shared.u64 t, %1; cvt.u32.u64 %0, t; }"
        : "=r"(a) : "l"(p));
    return a;
}

__device__ __forceinline__ void cp16(uint32_t dst, const void* src) {
    asm volatile("cp.async.ca.shared.global [%0], [%1], 16;"
                 :: "r"(dst), "l"(src) : "memory");
}
#define CP_COMMIT() asm volatile("cp.async.commit_group;" ::: "memory")
#define CP_WAIT1()  asm volatile("cp.async.wait_group 1;" ::: "memory")
#define CP_WAIT0()  asm volatile("cp.async.wait_group 0;" ::: "memory")

__device__ __forceinline__ uint32_t f2tf(float f) {
    uint32_t r;
    asm("cvt.rna.tf32.f32 %0, %1;" : "=r"(r) : "f"(f));
    return r;
}

__device__ __forceinline__ float ex2f(float x) {
    float r;
    asm("ex2.approx.f32 %0, %1;" : "=f"(r) : "f"(x));
    return r;
}

__device__ __forceinline__ void mma_tf32(
    float* c, const uint32_t* a, const uint32_t* b)
{
    asm volatile(
        "mma.sync.aligned.m16n8k8.row.col.f32.tf32.tf32.f32 "
        "{%0,%1,%2,%3}, {%4,%5,%6,%7}, {%8,%9}, {%0,%1,%2,%3};"
        : "+f"(c[0]), "+f"(c[1]), "+f"(c[2]), "+f"(c[3])
        : "r"(a[0]), "r"(a[1]), "r"(a[2]), "r"(a[3]),
          "r"(b[0]), "r"(b[1]));
}

// ===========================================================================
// TF32 mma.sync GEMM: C[M,N] = A[M,K] @ W[N,K]^T + bias (+ resid)
// CTA 128x128, BK=32, 8 warps (4M x 2N), warp tile 32x64 (2x8 m16n8k8).
// ===========================================================================
#define GK 32
#define GPAD 36
#define GTILE_FLOATS (128 * GPAD)
#define GTILE_BYTES  (GTILE_FLOATS * 4)
#define GEMM_SMEM    (4 * GTILE_BYTES)            // 73728

__global__ __launch_bounds__(256) void gemm_tf32(
    const float* __restrict__ A, const float* __restrict__ W,
    const float* __restrict__ bias, const float* __restrict__ resid,
    float* __restrict__ C, int M, int N, int K)
{
    extern __shared__ float sm[];
    float* As[2] = { sm,                  sm + GTILE_FLOATS };
    float* Bs[2] = { sm + 2*GTILE_FLOATS, sm + 3*GTILE_FLOATS };
    const uint32_t sA[2] = { smem_u32(As[0]), smem_u32(As[1]) };
    const uint32_t sB[2] = { smem_u32(Bs[0]), smem_u32(Bs[1]) };

    const int tid  = threadIdx.x;
    const int lane = tid & 31;
    const int wid  = tid >> 5;
    const int g    = lane >> 2;
    const int c    = lane & 3;
    const int wm0  = (wid & 3) * 32;
    const int wn0  = (wid >> 2) * 64;
    const int m0   = blockIdx.y * 128;
    const int n0   = blockIdx.x * 128;

    float acc[2][8][4];
#pragma unroll
    for (int mt = 0; mt < 2; mt++)
#pragma unroll
        for (int nt = 0; nt < 8; nt++)
#pragma unroll
            for (int k = 0; k < 4; k++) acc[mt][nt][k] = 0.f;

    const int nch = K >> 5;

    auto load_chunk = [&](int i, int st) {
        const float* Ag = A + (size_t)m0 * K + i * GK;
        const float* Wg = W + (size_t)n0 * K + i * GK;
#pragma unroll
        for (int t = 0; t < 4; t++) {
            const int idx = tid + t * 256;
            const int row = idx >> 3;
            const int q   = idx & 7;
            const uint32_t off = (uint32_t)(row * GPAD + q * 4) * 4u;
            cp16(sA[st] + off, Ag + (size_t)row * K + q * 4);
            cp16(sB[st] + off, Wg + (size_t)row * K + q * 4);
        }
        CP_COMMIT();
    };

    load_chunk(0, 0);

    for (int i = 0; i < nch; i++) {
        const int st = i & 1;
        if (i + 1 < nch) { load_chunk(i + 1, st ^ 1); CP_WAIT1(); }
        else             { CP_WAIT0(); }
        __syncthreads();

        const float* Af = As[st];
        const float* Bf = Bs[st];
#pragma unroll
        for (int kk = 0; kk < GK; kk += 8) {
            uint32_t af[2][4];
#pragma unroll
            for (int mt = 0; mt < 2; mt++) {
                const int m = wm0 + mt * 16 + g;
                af[mt][0] = f2tf(Af[(m    ) * GPAD + kk + c    ]);
                af[mt][1] = f2tf(Af[(m + 8) * GPAD + kk + c    ]);
                af[mt][2] = f2tf(Af[(m    ) * GPAD + kk + c + 4]);
                af[mt][3] = f2tf(Af[(m + 8) * GPAD + kk + c + 4]);
            }
            uint32_t bf[8][2];
#pragma unroll
            for (int nt = 0; nt < 8; nt++) {
                const int n = wn0 + nt * 8 + g;
                bf[nt][0] = f2tf(Bf[n * GPAD + kk + c    ]);
                bf[nt][1] = f2tf(Bf[n * GPAD + kk + c + 4]);
            }
#pragma unroll
            for (int mt = 0; mt < 2; mt++)
#pragma unroll
                for (int nt = 0; nt < 8; nt++)
                    mma_tf32(acc[mt][nt], af[mt], bf[nt]);
        }
        __syncthreads();
    }

#pragma unroll
    for (int mt = 0; mt < 2; mt++) {
#pragma unroll
        for (int hrow = 0; hrow < 2; hrow++) {
            const int m = m0 + wm0 + mt * 16 + g + hrow * 8;
#pragma unroll
            for (int nt = 0; nt < 8; nt++) {
                const int col = n0 + wn0 + nt * 8 + c * 2;
                float2 bi = *(const float2*)(bias + col);
                float2 v;
                v.x = acc[mt][nt][hrow * 2 + 0] + bi.x;
                v.y = acc[mt][nt][hrow * 2 + 1] + bi.y;
                if (resid) {
                    float2 r = *(const float2*)(resid + (size_t)m * N + col);
                    v.x += r.x; v.y += r.y;
                }
                *(float2*)(C + (size_t)m * N + col) = v;
            }
        }
    }
}

// ===========================================================================
// Tensor-core flash attention (tf32 mma.sync), causal + rel-pos bias.
// Block (qt,h,b): 128 threads / 4 warps; warp w owns q-rows [16w,16w+16).
// Q pre-scaled by SCALE*log2e; bias pre-scaled by log2e -> exp via ex2.
// ===========================================================================
#define QS_STR 68
#define VS_STR 72
#define QS_OFF 0
#define KS_OFF 4352                    // 64*68
#define VS_OFF (KS_OFF + 2 * 4352)    // 13056
#define BI_OFF (VS_OFF + 2 * 4608)    // 22272 (64*72 per stage)
#define ATTN_SMEM ((BI_OFF + 2 * 128) * 4)   // 90112 bytes

__global__ __launch_bounds__(128) void attn_mma(
    const float* __restrict__ qkv, const float* __restrict__ rpb,
    float* __restrict__ obuf)
{
    extern __shared__ float smf[];
    const uint32_t sbase = smem_u32(smf);
    float* Qs = smf + QS_OFF;            // reused as P tile
    uint32_t* PsU = (uint32_t*)Qs;

    const int qt = blockIdx.x;
    const int h  = blockIdx.y;
    const int b  = blockIdx.z;
    const int tid = threadIdx.x;
    const int w    = tid >> 5;
    const int lane = tid & 31;
    const int g    = lane >> 2;
    const int c    = lane & 3;
    const int q0   = qt * 64;
    const int r0   = w * 16 + g;         // this thread's first tile-local q row
    const int r1   = r0 + 8;

    // ---- Load Q tile (pre-scaled) ----
    const float CF = SCALE * LOG2E;
#pragma unroll
    for (int t = 0; t < 8; t++) {
        const int idx = tid + t * 128;
        const int r = idx >> 4, q = idx & 15;
        float4 v = *(const float4*)(qkv + (size_t)(b * SS + q0 + r) * D3 + h * HD + q * 4);
        v.x *= CF; v.y *= CF; v.z *= CF; v.w *= CF;
        *(float4*)(Qs + r * QS_STR + q * 4) = v;
    }
    __syncthreads();

    // ---- Extract Q fragments (held in registers for all k-tiles) ----
    uint32_t aq[8][4];
#pragma unroll
    for (int kk = 0; kk < 8; kk++) {
        const int col = kk * 8 + c;
        aq[kk][0] = f2tf(Qs[r0 * QS_STR + col    ]);
        aq[kk][1] = f2tf(Qs[r1 * QS_STR + col    ]);
        aq[kk][2] = f2tf(Qs[r0 * QS_STR + col + 4]);
        aq[kk][3] = f2tf(Qs[r1 * QS_STR + col + 4]);
    }
    __syncthreads();   // everyone done with Qs; it becomes the P tile

    float m0 = -1e30f, m1 = -1e30f, l0 = 0.f, l1 = 0.f;
    float o[8][4];
#pragma unroll
    for (int nt = 0; nt < 8; nt++)
#pragma unroll
        for (int k = 0; k < 4; k++) o[nt][k] = 0.f;

    auto loadKV = [&](int kt, int st) {
        const float* Kg = qkv + (size_t)(b * SS + kt * 64) * D3 + DD + h * HD;
        const float* Vg = qkv + (size_t)(b * SS + kt * 64) * D3 + 2 * DD + h * HD;
        const uint32_t kbase = sbase + (KS_OFF + st * 4352) * 4u;
        const uint32_t vbase = sbase + (VS_OFF + st * 4608) * 4u;
#pragma unroll
        for (int t = 0; t < 8; t++) {
            const int idx = tid + t * 128;
            const int r = idx >> 4, q = idx & 15;
            cp16(kbase + (uint32_t)(r * QS_STR + q * 4) * 4u, Kg + (size_t)r * D3 + q * 4);
            cp16(vbase + (uint32_t)(r * VS_STR + q * 4) * 4u, Vg + (size_t)r * D3 + q * 4);
        }
        // bias band: bias_s[j] = rpb[j-63 + kt*64 - q0 + 2047][h] * log2e
        {
            const int delta = tid - 63 + kt * 64 - q0;
            smf[BI_OFF + st * 128 + tid] = rpb[(size_t)(delta + SS - 1) * HH + h] * LOG2E;
        }
        CP_COMMIT();
    };

    loadKV(0, 0);

    for (int kt = 0; kt <= qt; kt++) {
        const int st = kt & 1;
        if (kt < qt) { loadKV(kt + 1, st ^ 1); CP_WAIT1(); }
        else         { CP_WAIT0(); }
        __syncthreads();

        const float* Ksp = smf + KS_OFF + st * 4352;
        const float* Vsp = smf + VS_OFF + st * 4608;
        const float* bsp = smf + BI_OFF + st * 128;
        const bool diag = (kt == qt);

        // ---- S = Qhat @ K^T (log2-domain scores) ----
        float s[8][4];
#pragma unroll
        for (int nt = 0; nt < 8; nt++)
#pragma unroll
            for (int k = 0; k < 4; k++) s[nt][k] = 0.f;

#pragma unroll
        for (int kk = 0; kk < 8; kk++) {
            uint32_t bf[8][2];
#pragma unroll
            for (int nt = 0; nt < 8; nt++) {
                const int n = nt * 8 + g;
                bf[nt][0] = f2tf(Ksp[n * QS_STR + kk * 8 + c    ]);
                bf[nt][1] = f2tf(Ksp[n * QS_STR + kk * 8 + c + 4]);
            }
#pragma unroll
            for (int nt = 0; nt < 8; nt++)
                mma_tf32(s[nt], aq[kk], bf[nt]);
        }

        // ---- bias + causal mask + tile max ----
        float tm0 = -1e30f, tm1 = -1e30f;
#pragma unroll
        for (int nt = 0; nt < 8; nt++) {
            const int col = nt * 8 + c * 2;
            s[nt][0] += bsp[col     - r0 + 63];
            s[nt][1] += bsp[col + 1 - r0 + 63];
            s[nt][2] += bsp[col     - r1 + 63];
            s[nt][3] += bsp[col + 1 - r1 + 63];
            if (diag) {
                if (col     > r0) s[nt][0] = -1e30f;
                if (col + 1 > r0) s[nt][1] = -1e30f;
                if (col     > r1) s[nt][2] = -1e30f;
                if (col + 1 > r1) s[nt][3] = -1e30f;
            }
            tm0 = fmaxf(tm0, fmaxf(s[nt][0], s[nt][1]));
            tm1 = fmaxf(tm1, fmaxf(s[nt][2], s[nt][3]));
        }
        tm0 = fmaxf(tm0, __shfl_xor_sync(0xffffffffu, tm0, 1));
        tm0 = fmaxf(tm0, __shfl_xor_sync(0xffffffffu, tm0, 2));
        tm1 = fmaxf(tm1, __shfl_xor_sync(0xffffffffu, tm1, 1));
        tm1 = fmaxf(tm1, __shfl_xor_sync(0xffffffffu, tm1, 2));

        const float mn0 = fmaxf(m0, tm0);
        const float mn1 = fmaxf(m1, tm1);
        const float alpha0 = ex2f(m0 - mn0);
        const float alpha1 = ex2f(m1 - mn1);
        m0 = mn0; m1 = mn1;

        // ---- P = 2^(s - m); write tf32 bits to smem; row sums ----
        float sum0 = 0.f, sum1 = 0.f;
#pragma unroll
        for (int nt = 0; nt < 8; nt++) {
            const int col = nt * 8 + c * 2;
            float p0 = ex2f(s[nt][0] - mn0);
            float p1 = ex2f(s[nt][1] - mn0);
            float p2 = ex2f(s[nt][2] - mn1);
            float p3 = ex2f(s[nt][3] - mn1);
            sum0 += p0 + p1;
            sum1 += p2 + p3;
            *(uint2*)&PsU[r0 * QS_STR + col] = make_uint2(f2tf(p0), f2tf(p1));
            *(uint2*)&PsU[r1 * QS_STR + col] = make_uint2(f2tf(p2), f2tf(p3));
        }
        sum0 += __shfl_xor_sync(0xffffffffu, sum0, 1);
        sum0 += __shfl_xor_sync(0xffffffffu, sum0, 2);
        sum1 += __shfl_xor_sync(0xffffffffu, sum1, 1);
        sum1 += __shfl_xor_sync(0xffffffffu, sum1, 2);
        l0 = l0 * alpha0 + sum0;
        l1 = l1 * alpha1 + sum1;

#pragma unroll
        for (int nt = 0; nt < 8; nt++) {
            o[nt][0] *= alpha0; o[nt][1] *= alpha0;
            o[nt][2] *= alpha1; o[nt][3] *= alpha1;
        }
        __syncwarp();

        // ---- O += P @ V  (V read transposed from row-major smem) ----
#pragma unroll
        for (int kk = 0; kk < 8; kk++) {
            uint32_t ap[4];
            ap[0] = PsU[r0 * QS_STR + kk * 8 + c    ];
            ap[1] = PsU[r1 * QS_STR + kk * 8 + c    ];
            ap[2] = PsU[r0 * QS_STR + kk * 8 + c + 4];
            ap[3] = PsU[r1 * QS_STR + kk * 8 + c + 4];
            uint32_t bv[8][2];
#pragma unroll
            for (int nt = 0; nt < 8; nt++) {
                const int n = nt * 8 + g;
                bv[nt][0] = f2tf(Vsp[(kk * 8 + c    ) * VS_STR + n]);
                bv[nt][1] = f2tf(Vsp[(kk * 8 + c + 4) * VS_STR + n]);
            }
#pragma unroll
            for (int nt = 0; nt < 8; nt++)
                mma_tf32(o[nt], ap, bv[nt]);
        }
        __syncthreads();
    }

    // ---- Normalize + write ----
    const float inv0 = 1.f / l0;
    const float inv1 = 1.f / l1;
    const size_t base0 = (size_t)(b * SS + q0 + r0) * DD + h * HD;
    const size_t base1 = (size_t)(b * SS + q0 + r1) * DD + h * HD;
#pragma unroll
    for (int nt = 0; nt < 8; nt++) {
        const int col = nt * 8 + c * 2;
        *(float2*)(obuf + base0 + col) = make_float2(o[nt][0] * inv0, o[nt][1] * inv0);
        *(float2*)(obuf + base1 + col) = make_float2(o[nt][2] * inv1, o[nt][3] * inv1);
    }
}

// ---------------------------------------------------------------------------
// LayerNorm over D=1024
// ---------------------------------------------------------------------------
__global__ __launch_bounds__(256) void layernorm_k(
    const float* __restrict__ y, const float* __restrict__ g,
    const float* __restrict__ bta, float* __restrict__ out)
{
    const int row = blockIdx.x;
    const int t = threadIdx.x;
    const float4 v = *(const float4*)(y + (size_t)row * DD + t * 4);

    float s  = v.x + v.y + v.z + v.w;
    float sq = v.x * v.x + v.y * v.y + v.z * v.z + v.w * v.w;
#pragma unroll
    for (int off = 16; off > 0; off >>= 1) {
        s  += __shfl_xor_sync(0xffffffffu, s, off);
        sq += __shfl_xor_sync(0xffffffffu, sq, off);
    }
    __shared__ float ss[8], sqq[8];
    if ((t & 31) == 0) { ss[t >> 5] = s; sqq[t >> 5] = sq; }
    __syncthreads();
    float tot = 0.f, totq = 0.f;
#pragma unroll
    for (int i = 0; i < 8; i++) { tot += ss[i]; totq += sqq[i]; }
    const float mu  = tot * (1.f / DD);
    const float var = totq * (1.f / DD) - mu * mu;
    const float r   = rsqrtf(var + LN_EPS);

    const float4 gg = *(const float4*)(g + t * 4);
    const float4 bb = *(const float4*)(bta + t * 4);
    float4 o4;
    o4.x = (v.x - mu) * r * gg.x + bb.x;
    o4.y = (v.y - mu) * r * gg.y + bb.y;
    o4.z = (v.z - mu) * r * gg.z + bb.z;
    o4.w = (v.w - mu) * r * gg.w + bb.w;
    *(float4*)(out + (size_t)row * DD + t * 4) = o4;
}

// ---------------------------------------------------------------------------
// Launch
// ---------------------------------------------------------------------------
extern "C" void kernel_launch(void* const* d_in, const int* in_sizes, int n_in,
                              void* d_out, int out_size)
{
    const float* x      = (const float*)d_in[0];
    const float* W_w    = (const float*)d_in[1];
    const float* W_b    = (const float*)d_in[2];
    const float* proj_w = (const float*)d_in[3];
    const float* proj_b = (const float*)d_in[4];
    const float* ln_g   = (const float*)d_in[5];
    const float* ln_b   = (const float*)d_in[6];
    const float* rpb    = (const float*)d_in[7];
    float* out = (float*)d_out;

    float *qkv, *obuf, *ybuf;
    cudaGetSymbolAddress((void**)&qkv,  g_qkv);
    cudaGetSymbolAddress((void**)&obuf, g_o);
    cudaGetSymbolAddress((void**)&ybuf, g_y);

    cudaFuncSetAttribute(gemm_tf32, cudaFuncAttributeMaxDynamicSharedMemorySize, GEMM_SMEM);
    cudaFuncSetAttribute(attn_mma, cudaFuncAttributeMaxDynamicSharedMemorySize, ATTN_SMEM);

    // 1) QKV projection
    {
        dim3 grid(D3 / 128, MROWS / 128);
        gemm_tf32<<<grid, 256, GEMM_SMEM>>>(x, W_w, W_b, nullptr, qkv, MROWS, D3, DD);
    }

    // 2) Flash attention (tensor cores)
    {
        dim3 grid(SS / 64, HH, BB);
        attn_mma<<<grid, 128, ATTN_SMEM>>>(qkv, rpb, obuf);
    }

    // 3) Output projection + residual
    {
        dim3 grid(DD / 128, MROWS / 128);
        gemm_tf32<<<grid, 256, GEMM_SMEM>>>(obuf, proj_w, proj_b, x, ybuf, MROWS, DD, DD);
    }

    // 4) LayerNorm
    layernorm_k<<<MROWS, 256>>>(ybuf, ln_g, ln_b, out);
}

// round 5
// speedup vs baseline: 3.6239x; 1.1034x over previous
#include <cuda_runtime.h>
#include <cuda_bf16.h>
#include <cstdint>

// Problem constants
#define BB 2
#define SS 2048
#define DD 1024
#define HH 16
#define HD 64
#define D3 3072
#define MROWS (BB * SS)          // 4096
#define SCALE 0.03125f           // 1/sqrt(1024)
#define LOG2E 1.4426950408889634f
#define LN_EPS 1e-5f

// ---------------------------------------------------------------------------
// Scratch (no allocation allowed -> __device__ globals)
// ---------------------------------------------------------------------------
__device__ float g_qkv[MROWS * D3];     // 48 MB (tf32-rounded values)
__device__ float g_o[MROWS * DD];       // 16 MB (attention out, tf32-rounded)
__device__ float g_y[MROWS * DD];       // 16 MB (proj + residual, fp32)
__device__ float g_xr[MROWS * DD];      // 16 MB (x, tf32-rounded)
__device__ float g_wr[D3 * DD];         // 12 MB (W_w, tf32-rounded)
__device__ float g_pwr[DD * DD];        //  4 MB (proj_w, tf32-rounded)

// ---------------------------------------------------------------------------
// Portable helpers (sm_80+ only; NO sm_100a-gated instructions)
// ---------------------------------------------------------------------------
__device__ __forceinline__ uint32_t smem_u32(const void* p) {
    uint32_t a;
    asm("{ .reg .u64 t; cvta.to.shared.u64 t, %1; cvt.u32.u64 %0, t; }"
        : "=r"(a) : "l"(p));
    return a;
}

__device__ __forceinline__ void cp16(uint32_t dst, const void* src) {
    asm volatile("cp.async.ca.shared.global [%0], [%1], 16;"
                 :: "r"(dst), "l"(src) : "memory");
}
#define CP_COMMIT() asm volatile("cp.async.commit_group;" ::: "memory")
#define CP_WAIT1()  asm volatile("cp.async.wait_group 1;" ::: "memory")
#define CP_WAIT0()  asm volatile("cp.async.wait_group 0;" ::: "memory")

__device__ __forceinline__ uint32_t f2tf(float f) {
    uint32_t r;
    asm("cvt.rna.tf32.f32 %0, %1;" : "=r"(r) : "f"(f));
    return r;
}
__device__ __forceinline__ float roundtf(float f) {
    return __uint_as_float(f2tf(f));
}

__device__ __forceinline__ float ex2f(float x) {
    float r;
    asm("ex2.approx.f32 %0, %1;" : "=f"(r) : "f"(x));
    return r;
}

__device__ __forceinline__ void mma_tf32(
    float* c, const uint32_t* a, const uint32_t* b)
{
    asm volatile(
        "mma.sync.aligned.m16n8k8.row.col.f32.tf32.tf32.f32 "
        "{%0,%1,%2,%3}, {%4,%5,%6,%7}, {%8,%9}, {%0,%1,%2,%3};"
        : "+f"(c[0]), "+f"(c[1]), "+f"(c[2]), "+f"(c[3])
        : "r"(a[0]), "r"(a[1]), "r"(a[2]), "r"(a[3]),
          "r"(b[0]), "r"(b[1]));
}

// ---------------------------------------------------------------------------
// Pre-round fp32 -> tf32-rounded fp32 (elementwise, vectorized)
// ---------------------------------------------------------------------------
__global__ __launch_bounds__(256) void round_tf32_k(
    const float* __restrict__ in, float* __restrict__ out, int n4)
{
    const int i = blockIdx.x * 256 + threadIdx.x;
    if (i < n4) {
        float4 v = *(const float4*)(in + (size_t)i * 4);
        v.x = roundtf(v.x); v.y = roundtf(v.y);
        v.z = roundtf(v.z); v.w = roundtf(v.w);
        *(float4*)(out + (size_t)i * 4) = v;
    }
}

// ===========================================================================
// TF32 mma.sync GEMM: C[M,N] = A[M,K] @ W[N,K]^T + bias (+ resid)
// A, W must be tf32-pre-rounded. Fragments are raw smem bits (no cvt).
// CTA 128x128, BK=32, 8 warps (4M x 2N), warp tile 32x64 (2x8 m16n8k8).
// ===========================================================================
#define GK 32
#define GPAD 36
#define GTILE_FLOATS (128 * GPAD)
#define GTILE_BYTES  (GTILE_FLOATS * 4)
#define GEMM_SMEM    (4 * GTILE_BYTES)            // 73728

__global__ __launch_bounds__(256) void gemm_tf32(
    const float* __restrict__ A, const float* __restrict__ W,
    const float* __restrict__ bias, const float* __restrict__ resid,
    float* __restrict__ C, int M, int N, int K, int round_out)
{
    extern __shared__ float sm[];
    float* As[2] = { sm,                  sm + GTILE_FLOATS };
    float* Bs[2] = { sm + 2*GTILE_FLOATS, sm + 3*GTILE_FLOATS };
    const uint32_t sA[2] = { smem_u32(As[0]), smem_u32(As[1]) };
    const uint32_t sB[2] = { smem_u32(Bs[0]), smem_u32(Bs[1]) };

    const int tid  = threadIdx.x;
    const int lane = tid & 31;
    const int wid  = tid >> 5;
    const int g    = lane >> 2;
    const int c    = lane & 3;
    const int wm0  = (wid & 3) * 32;
    const int wn0  = (wid >> 2) * 64;
    const int m0   = blockIdx.y * 128;
    const int n0   = blockIdx.x * 128;

    float acc[2][8][4];
#pragma unroll
    for (int mt = 0; mt < 2; mt++)
#pragma unroll
        for (int nt = 0; nt < 8; nt++)
#pragma unroll
            for (int k = 0; k < 4; k++) acc[mt][nt][k] = 0.f;

    const int nch = K >> 5;

    auto load_chunk = [&](int i, int st) {
        const float* Ag = A + (size_t)m0 * K + i * GK;
        const float* Wg = W + (size_t)n0 * K + i * GK;
#pragma unroll
        for (int t = 0; t < 4; t++) {
            const int idx = tid + t * 256;
            const int row = idx >> 3;
            const int q   = idx & 7;
            const uint32_t off = (uint32_t)(row * GPAD + q * 4) * 4u;
            cp16(sA[st] + off, Ag + (size_t)row * K + q * 4);
            cp16(sB[st] + off, Wg + (size_t)row * K + q * 4);
        }
        CP_COMMIT();
    };

    load_chunk(0, 0);

    for (int i = 0; i < nch; i++) {
        const int st = i & 1;
        if (i + 1 < nch) { load_chunk(i + 1, st ^ 1); CP_WAIT1(); }
        else             { CP_WAIT0(); }
        __syncthreads();

        const uint32_t* Af = (const uint32_t*)As[st];
        const uint32_t* Bf = (const uint32_t*)Bs[st];
#pragma unroll
        for (int kk = 0; kk < GK; kk += 8) {
            uint32_t af[2][4];
#pragma unroll
            for (int mt = 0; mt < 2; mt++) {
                const int m = wm0 + mt * 16 + g;
                af[mt][0] = Af[(m    ) * GPAD + kk + c    ];
                af[mt][1] = Af[(m + 8) * GPAD + kk + c    ];
                af[mt][2] = Af[(m    ) * GPAD + kk + c + 4];
                af[mt][3] = Af[(m + 8) * GPAD + kk + c + 4];
            }
            uint32_t bf[8][2];
#pragma unroll
            for (int nt = 0; nt < 8; nt++) {
                const int n = wn0 + nt * 8 + g;
                bf[nt][0] = Bf[n * GPAD + kk + c    ];
                bf[nt][1] = Bf[n * GPAD + kk + c + 4];
            }
#pragma unroll
            for (int mt = 0; mt < 2; mt++)
#pragma unroll
                for (int nt = 0; nt < 8; nt++)
                    mma_tf32(acc[mt][nt], af[mt], bf[nt]);
        }
        __syncthreads();
    }

#pragma unroll
    for (int mt = 0; mt < 2; mt++) {
#pragma unroll
        for (int hrow = 0; hrow < 2; hrow++) {
            const int m = m0 + wm0 + mt * 16 + g + hrow * 8;
#pragma unroll
            for (int nt = 0; nt < 8; nt++) {
                const int col = n0 + wn0 + nt * 8 + c * 2;
                float2 bi = *(const float2*)(bias + col);
                float2 v;
                v.x = acc[mt][nt][hrow * 2 + 0] + bi.x;
                v.y = acc[mt][nt][hrow * 2 + 1] + bi.y;
                if (resid) {
                    float2 r = *(const float2*)(resid + (size_t)m * N + col);
                    v.x += r.x; v.y += r.y;
                }
                if (round_out) { v.x = roundtf(v.x); v.y = roundtf(v.y); }
                *(float2*)(C + (size_t)m * N + col) = v;
            }
        }
    }
}

// ===========================================================================
// Tensor-core flash attention (tf32 mma.sync), causal + rel-pos bias.
// qkv must be tf32-pre-rounded -> K/V fragments are raw bits (no cvt).
// Block (qt,h,b): 128 threads / 4 warps; warp w owns q-rows [16w,16w+16).
// ===========================================================================
#define QS_STR 68
#define VS_STR 72
#define QS_OFF 0
#define KS_OFF 4352                    // 64*68
#define VS_OFF (KS_OFF + 2 * 4352)    // 13056
#define BI_OFF (VS_OFF + 2 * 4608)    // 22272
#define ATTN_SMEM ((BI_OFF + 2 * 128) * 4)   // 90112 bytes

__global__ __launch_bounds__(128) void attn_mma(
    const float* __restrict__ qkv, const float* __restrict__ rpb,
    float* __restrict__ obuf)
{
    extern __shared__ float smf[];
    const uint32_t sbase = smem_u32(smf);
    float* Qs = smf + QS_OFF;            // reused as P tile
    uint32_t* PsU = (uint32_t*)Qs;

    const int qt = blockIdx.x;
    const int h  = blockIdx.y;
    const int b  = blockIdx.z;
    const int tid = threadIdx.x;
    const int w    = tid >> 5;
    const int lane = tid & 31;
    const int g    = lane >> 2;
    const int c    = lane & 3;
    const int q0   = qt * 64;
    const int r0   = w * 16 + g;
    const int r1   = r0 + 8;

    // ---- Load Q tile (pre-scaled) ----
    const float CF = SCALE * LOG2E;
#pragma unroll
    for (int t = 0; t < 8; t++) {
        const int idx = tid + t * 128;
        const int r = idx >> 4, q = idx & 15;
        float4 v = *(const float4*)(qkv + (size_t)(b * SS + q0 + r) * D3 + h * HD + q * 4);
        v.x *= CF; v.y *= CF; v.z *= CF; v.w *= CF;
        *(float4*)(Qs + r * QS_STR + q * 4) = v;
    }
    __syncthreads();

    // ---- Extract Q fragments (rescaled -> re-round once) ----
    uint32_t aq[8][4];
#pragma unroll
    for (int kk = 0; kk < 8; kk++) {
        const int col = kk * 8 + c;
        aq[kk][0] = f2tf(Qs[r0 * QS_STR + col    ]);
        aq[kk][1] = f2tf(Qs[r1 * QS_STR + col    ]);
        aq[kk][2] = f2tf(Qs[r0 * QS_STR + col + 4]);
        aq[kk][3] = f2tf(Qs[r1 * QS_STR + col + 4]);
    }
    __syncthreads();   // Qs becomes the P tile

    float m0 = -1e30f, m1 = -1e30f, l0 = 0.f, l1 = 0.f;
    float o[8][4];
#pragma unroll
    for (int nt = 0; nt < 8; nt++)
#pragma unroll
        for (int k = 0; k < 4; k++) o[nt][k] = 0.f;

    auto loadKV = [&](int kt, int st) {
        const float* Kg = qkv + (size_t)(b * SS + kt * 64) * D3 + DD + h * HD;
        const float* Vg = qkv + (size_t)(b * SS + kt * 64) * D3 + 2 * DD + h * HD;
        const uint32_t kbase = sbase + (KS_OFF + st * 4352) * 4u;
        const uint32_t vbase = sbase + (VS_OFF + st * 4608) * 4u;
#pragma unroll
        for (int t = 0; t < 8; t++) {
            const int idx = tid + t * 128;
            const int r = idx >> 4, q = idx & 15;
            cp16(kbase + (uint32_t)(r * QS_STR + q * 4) * 4u, Kg + (size_t)r * D3 + q * 4);
            cp16(vbase + (uint32_t)(r * VS_STR + q * 4) * 4u, Vg + (size_t)r * D3 + q * 4);
        }
        {
            const int delta = tid - 63 + kt * 64 - q0;
            smf[BI_OFF + st * 128 + tid] = rpb[(size_t)(delta + SS - 1) * HH + h] * LOG2E;
        }
        CP_COMMIT();
    };

    loadKV(0, 0);

    for (int kt = 0; kt <= qt; kt++) {
        const int st = kt & 1;
        if (kt < qt) { loadKV(kt + 1, st ^ 1); CP_WAIT1(); }
        else         { CP_WAIT0(); }
        __syncthreads();

        const uint32_t* KsU = (const uint32_t*)(smf + KS_OFF + st * 4352);
        const uint32_t* VsU = (const uint32_t*)(smf + VS_OFF + st * 4608);
        const float* bsp = smf + BI_OFF + st * 128;
        const bool diag = (kt == qt);

        // ---- S = Qhat @ K^T ----
        float s[8][4];
#pragma unroll
        for (int nt = 0; nt < 8; nt++)
#pragma unroll
            for (int k = 0; k < 4; k++) s[nt][k] = 0.f;

#pragma unroll
        for (int kk = 0; kk < 8; kk++) {
            uint32_t bf[8][2];
#pragma unroll
            for (int nt = 0; nt < 8; nt++) {
                const int n = nt * 8 + g;
                bf[nt][0] = KsU[n * QS_STR + kk * 8 + c    ];
                bf[nt][1] = KsU[n * QS_STR + kk * 8 + c + 4];
            }
#pragma unroll
            for (int nt = 0; nt < 8; nt++)
                mma_tf32(s[nt], aq[kk], bf[nt]);
        }

        // ---- bias + causal mask + tile max ----
        float tm0 = -1e30f, tm1 = -1e30f;
#pragma unroll
        for (int nt = 0; nt < 8; nt++) {
            const int col = nt * 8 + c * 2;
            s[nt][0] += bsp[col     - r0 + 63];
            s[nt][1] += bsp[col + 1 - r0 + 63];
            s[nt][2] += bsp[col     - r1 + 63];
            s[nt][3] += bsp[col + 1 - r1 + 63];
            if (diag) {
                if (col     > r0) s[nt][0] = -1e30f;
                if (col + 1 > r0) s[nt][1] = -1e30f;
                if (col     > r1) s[nt][2] = -1e30f;
                if (col + 1 > r1) s[nt][3] = -1e30f;
            }
            tm0 = fmaxf(tm0, fmaxf(s[nt][0], s[nt][1]));
            tm1 = fmaxf(tm1, fmaxf(s[nt][2], s[nt][3]));
        }
        tm0 = fmaxf(tm0, __shfl_xor_sync(0xffffffffu, tm0, 1));
        tm0 = fmaxf(tm0, __shfl_xor_sync(0xffffffffu, tm0, 2));
        tm1 = fmaxf(tm1, __shfl_xor_sync(0xffffffffu, tm1, 1));
        tm1 = fmaxf(tm1, __shfl_xor_sync(0xffffffffu, tm1, 2));

        const float mn0 = fmaxf(m0, tm0);
        const float mn1 = fmaxf(m1, tm1);
        const float alpha0 = ex2f(m0 - mn0);
        const float alpha1 = ex2f(m1 - mn1);
        m0 = mn0; m1 = mn1;

        // ---- P = 2^(s - m); tf32 bits to smem; row sums ----
        float sum0 = 0.f, sum1 = 0.f;
#pragma unroll
        for (int nt = 0; nt < 8; nt++) {
            const int col = nt * 8 + c * 2;
            float p0 = ex2f(s[nt][0] - mn0);
            float p1 = ex2f(s[nt][1] - mn0);
            float p2 = ex2f(s[nt][2] - mn1);
            float p3 = ex2f(s[nt][3] - mn1);
            sum0 += p0 + p1;
            sum1 += p2 + p3;
            *(uint2*)&PsU[r0 * QS_STR + col] = make_uint2(f2tf(p0), f2tf(p1));
            *(uint2*)&PsU[r1 * QS_STR + col] = make_uint2(f2tf(p2), f2tf(p3));
        }
        sum0 += __shfl_xor_sync(0xffffffffu, sum0, 1);
        sum0 += __shfl_xor_sync(0xffffffffu, sum0, 2);
        sum1 += __shfl_xor_sync(0xffffffffu, sum1, 1);
        sum1 += __shfl_xor_sync(0xffffffffu, sum1, 2);
        l0 = l0 * alpha0 + sum0;
        l1 = l1 * alpha1 + sum1;

#pragma unroll
        for (int nt = 0; nt < 8; nt++) {
            o[nt][0] *= alpha0; o[nt][1] *= alpha0;
            o[nt][2] *= alpha1; o[nt][3] *= alpha1;
        }
        __syncwarp();

        // ---- O += P @ V (V raw bits, read transposed) ----
#pragma unroll
        for (int kk = 0; kk < 8; kk++) {
            uint32_t ap[4];
            ap[0] = PsU[r0 * QS_STR + kk * 8 + c    ];
            ap[1] = PsU[r1 * QS_STR + kk * 8 + c    ];
            ap[2] = PsU[r0 * QS_STR + kk * 8 + c + 4];
            ap[3] = PsU[r1 * QS_STR + kk * 8 + c + 4];
            uint32_t bv[8][2];
#pragma unroll
            for (int nt = 0; nt < 8; nt++) {
                const int n = nt * 8 + g;
                bv[nt][0] = VsU[(kk * 8 + c    ) * VS_STR + n];
                bv[nt][1] = VsU[(kk * 8 + c + 4) * VS_STR + n];
            }
#pragma unroll
            for (int nt = 0; nt < 8; nt++)
                mma_tf32(o[nt], ap, bv[nt]);
        }
        __syncthreads();
    }

    // ---- Normalize + write (tf32-rounded for proj GEMM) ----
    const float inv0 = 1.f / l0;
    const float inv1 = 1.f / l1;
    const size_t base0 = (size_t)(b * SS + q0 + r0) * DD + h * HD;
    const size_t base1 = (size_t)(b * SS + q0 + r1) * DD + h * HD;
#pragma unroll
    for (int nt = 0; nt < 8; nt++) {
        const int col = nt * 8 + c * 2;
        *(float2*)(obuf + base0 + col) =
            make_float2(roundtf(o[nt][0] * inv0), roundtf(o[nt][1] * inv0));
        *(float2*)(obuf + base1 + col) =
            make_float2(roundtf(o[nt][2] * inv1), roundtf(o[nt][3] * inv1));
    }
}

// ---------------------------------------------------------------------------
// LayerNorm over D=1024
// ---------------------------------------------------------------------------
__global__ __launch_bounds__(256) void layernorm_k(
    const float* __restrict__ y, const float* __restrict__ g,
    const float* __restrict__ bta, float* __restrict__ out)
{
    const int row = blockIdx.x;
    const int t = threadIdx.x;
    const float4 v = *(const float4*)(y + (size_t)row * DD + t * 4);

    float s  = v.x + v.y + v.z + v.w;
    float sq = v.x * v.x + v.y * v.y + v.z * v.z + v.w * v.w;
#pragma unroll
    for (int off = 16; off > 0; off >>= 1) {
        s  += __shfl_xor_sync(0xffffffffu, s, off);
        sq += __shfl_xor_sync(0xffffffffu, sq, off);
    }
    __shared__ float ss[8], sqq[8];
    if ((t & 31) == 0) { ss[t >> 5] = s; sqq[t >> 5] = sq; }
    __syncthreads();
    float tot = 0.f, totq = 0.f;
#pragma unroll
    for (int i = 0; i < 8; i++) { tot += ss[i]; totq += sqq[i]; }
    const float mu  = tot * (1.f / DD);
    const float var = totq * (1.f / DD) - mu * mu;
    const float r   = rsqrtf(var + LN_EPS);

    const float4 gg = *(const float4*)(g + t * 4);
    const float4 bb = *(const float4*)(bta + t * 4);
    float4 o4;
    o4.x = (v.x - mu) * r * gg.x + bb.x;
    o4.y = (v.y - mu) * r * gg.y + bb.y;
    o4.z = (v.z - mu) * r * gg.z + bb.z;
    o4.w = (v.w - mu) * r * gg.w + bb.w;
    *(float4*)(out + (size_t)row * DD + t * 4) = o4;
}

// ---------------------------------------------------------------------------
// Launch
// ---------------------------------------------------------------------------
extern "C" void kernel_launch(void* const* d_in, const int* in_sizes, int n_in,
                              void* d_out, int out_size)
{
    const float* x      = (const float*)d_in[0];
    const float* W_w    = (const float*)d_in[1];
    const float* W_b    = (const float*)d_in[2];
    const float* proj_w = (const float*)d_in[3];
    const float* proj_b = (const float*)d_in[4];
    const float* ln_g   = (const float*)d_in[5];
    const float* ln_b   = (const float*)d_in[6];
    const float* rpb    = (const float*)d_in[7];
    float* out = (float*)d_out;

    float *qkv, *obuf, *ybuf, *xr, *wr, *pwr;
    cudaGetSymbolAddress((void**)&qkv,  g_qkv);
    cudaGetSymbolAddress((void**)&obuf, g_o);
    cudaGetSymbolAddress((void**)&ybuf, g_y);
    cudaGetSymbolAddress((void**)&xr,   g_xr);
    cudaGetSymbolAddress((void**)&wr,   g_wr);
    cudaGetSymbolAddress((void**)&pwr,  g_pwr);

    cudaFuncSetAttribute(gemm_tf32, cudaFuncAttributeMaxDynamicSharedMemorySize, GEMM_SMEM);
    cudaFuncSetAttribute(attn_mma, cudaFuncAttributeMaxDynamicSharedMemorySize, ATTN_SMEM);

    // 0) Pre-round inputs to tf32 values
    round_tf32_k<<<(MROWS * DD / 4 + 255) / 256, 256>>>(x, xr, MROWS * DD / 4);
    round_tf32_k<<<(D3 * DD / 4 + 255) / 256, 256>>>(W_w, wr, D3 * DD / 4);
    round_tf32_k<<<(DD * DD / 4 + 255) / 256, 256>>>(proj_w, pwr, DD * DD / 4);

    // 1) QKV projection (outputs rounded for attention)
    {
        dim3 grid(D3 / 128, MROWS / 128);
        gemm_tf32<<<grid, 256, GEMM_SMEM>>>(xr, wr, W_b, nullptr, qkv, MROWS, D3, DD, 1);
    }

    // 2) Flash attention (tensor cores, zero cvts in kt loop)
    {
        dim3 grid(SS / 64, HH, BB);
        attn_mma<<<grid, 128, ATTN_SMEM>>>(qkv, rpb, obuf);
    }

    // 3) Output projection + residual (resid = original fp32 x)
    {
        dim3 grid(DD / 128, MROWS / 128);
        gemm_tf32<<<grid, 256, GEMM_SMEM>>>(obuf, pwr, proj_b, x, ybuf, MROWS, DD, DD, 0);
    }

    // 4) LayerNorm
    layernorm_k<<<MROWS, 256>>>(ybuf, ln_g, ln_b, out);
}